// round 16
// baseline (speedup 1.0000x reference)
#include <cuda_runtime.h>
#include <cuda_fp16.h>

// ---------------------------------------------------------------------------
// GIN regressor (sm_103): HMMA fp16 3-pass split GEMMs + CSR gather.
// R16 = R15 with the double-buffer parity bug fixed: buffer selected by the
// block-local iteration counter (ib ^= 1), NOT tile index (stride 304 is even
// so (it & 1) was constant and prefetch clobbered the live buffer / T1).
// Launches: hist+setup(0) scan_part(1) scan_bcast(2) fill(3)<-profiled
//           gather(4) mlp1(5) gather(6) mlp2(7)
// ---------------------------------------------------------------------------

#define NODES 100000
#define EMAX  600000
#define DIM   128
#define SCAN_BLKS ((NODES + 255) / 256)          // 391

__device__ __align__(16) unsigned short g_ahi[NODES * DIM];  // split agg, hi plane
__device__ __align__(16) unsigned short g_alo[NODES * DIM];  // split agg, lo plane
__device__ __align__(16) float g_h1 [NODES * DIM];
__device__ __align__(16) unsigned short g_wblob[3 * 2 * 128 * 144];
__device__ __align__(16) float g_wv[DIM];
__device__ float g_cb;
__device__ int   g_cnt[NODES];          // zero-init; scan_bcast resets
__device__ int   g_part[SCAN_BLKS];
__device__ int   g_rowp[NODES + 1];
__device__ int   g_cursor[NODES];
__device__ int   g_srcs[EMAX];

// ------------------------------ helpers ------------------------------------
__device__ __forceinline__ unsigned smem_u32(const void* p) {
    unsigned a;
    asm("{ .reg .u64 t; cvta.to.shared.u64 t, %1; cvt.u32.u64 %0, t; }"
        : "=r"(a) : "l"(p));
    return a;
}
// volatile+memory: A smem buffers are rewritten (epilogue1 / prefetch) and
// re-read at the same addresses across loop iterations.
__device__ __forceinline__ void ldm4(unsigned* r, unsigned addr) {
    asm volatile("ldmatrix.sync.aligned.m8n8.x4.shared.b16 {%0,%1,%2,%3}, [%4];"
                 : "=r"(r[0]), "=r"(r[1]), "=r"(r[2]), "=r"(r[3]) : "r"(addr)
                 : "memory");
}
__device__ __forceinline__ void sts32(unsigned addr, unsigned v) {
    asm volatile("st.shared.u32 [%0], %1;" :: "r"(addr), "r"(v) : "memory");
}
__device__ __forceinline__ void mma_hf(float* c, const unsigned* a, uint2 b) {
    asm ("mma.sync.aligned.m16n8k16.row.col.f32.f16.f16.f32 "
         "{%0,%1,%2,%3}, {%4,%5,%6,%7}, {%8,%9}, {%0,%1,%2,%3};"
         : "+f"(c[0]), "+f"(c[1]), "+f"(c[2]), "+f"(c[3])
         : "r"(a[0]), "r"(a[1]), "r"(a[2]), "r"(a[3]), "r"(b.x), "r"(b.y));
}
__device__ __forceinline__ void split_f16(float a, unsigned short& hi, unsigned short& lo) {
    __half h = __float2half_rn(a);
    hi = __half_as_ushort(h);
    lo = __half_as_ushort(__float2half_rn(a - __half2float(h)));
}

#define AS_STRIDE 136
#define WS_STRIDE 144
#define W_ONE     (128 * WS_STRIDE)
#define W_ONE_B   (W_ONE * 2)           // 36864
#define W_PAIR_B  (2 * W_ONE_B)         // 73728

#define TROWS 64
#define ABUF_B   (2 * TROWS * AS_STRIDE * 2)    // 34816 (hi+lo planes)
#define OFF_ALO  (TROWS * AS_STRIDE * 2)        // 17408 (within a buffer)
#define SMEM_MLP (2 * ABUF_B)                   // 69632 -> 2 blocks/SM

#define NT_STEP_B (8 * WS_STRIDE * 2)           // 2304
#define PGRID 304                               // persistent grid (2/SM x 152)

// ------------------------- hist + setup (launch 0) ---------------------------
__device__ __forceinline__ int detect_ei(const unsigned int* ei) {
    unsigned orv = 0;
#pragma unroll
    for (int i = 0; i < 64; ++i) orv |= ei[2 * i + 1];
    return (orv == 0u) ? 1 : 0;
}

// 4 edges per thread; E % 4 == 0 so groups are all-or-nothing.
__device__ __forceinline__ void load4_idx(const void* eiv, int ef, int base,
                                          int off, int* d) {
    if (ef) {
        const long long* p = (const long long*)eiv + off + base;
        longlong2 a = *(const longlong2*)p;
        longlong2 b = *(const longlong2*)(p + 2);
        d[0] = (int)a.x; d[1] = (int)a.y; d[2] = (int)b.x; d[3] = (int)b.y;
    } else {
        const int* p = (const int*)eiv + off + base;
        int4 a = *(const int4*)p;
        d[0] = a.x; d[1] = a.y; d[2] = a.z; d[3] = a.w;
    }
}

__global__ void hist_setup_kernel(const void* __restrict__ eiv, int E, int edgeBlocks,
                                  const float* __restrict__ w1a,
                                  const float* __restrict__ w1b,
                                  const float* __restrict__ w2a,
                                  const float* __restrict__ w2b,
                                  const float* __restrict__ b2b,
                                  const float* __restrict__ wo,
                                  const float* __restrict__ bo) {
    int b = blockIdx.x, t = threadIdx.x;
    if (b < edgeBlocks) {                       // histogram: 1024 edges/block
        __shared__ int s_ef;
        if (t == 0) s_ef = detect_ei((const unsigned int*)eiv);
        __syncthreads();
        int base = b * 1024 + t * 4;
        if (base >= E) return;
        int d[4];
        load4_idx(eiv, s_ef, base, E, d);
        atomicAdd(&g_cnt[d[0]], 1);
        atomicAdd(&g_cnt[d[1]], 1);
        atomicAdd(&g_cnt[d[2]], 1);
        atomicAdd(&g_cnt[d[3]], 1);
        return;
    }
    int sb = b - edgeBlocks;                    // setup part
    if (sb == 0) {
        if (t < 128) {
            float s = 0.f;
#pragma unroll 8
            for (int n = 0; n < DIM; ++n) s += w2b[t * DIM + n] * wo[n];
            g_wv[t] = s;
            if (t == 0) {
                float c = bo[0];
                for (int n = 0; n < DIM; ++n) c += b2b[n] * wo[n];
                g_cb = c;
            }
        }
    } else {
        int i = (sb - 1) * 256 + t;
        int slot = i / W_ONE;
        int j    = i - slot * W_ONE;
        const float* w = (slot == 0) ? w1a : (slot == 1) ? w1b : w2a;
        unsigned short* hiB = g_wblob + (size_t)slot * 2 * W_ONE;
        unsigned short* loB = hiB + W_ONE;
        int n  = j / WS_STRIDE;
        int kp = j - n * WS_STRIDE;
        if (kp >= 128) { hiB[j] = 0; loB[j] = 0; }
        else {
            int chunk = kp >> 4, p = kp & 15;
            int tt = p >> 2, bb = (p >> 1) & 1, jj = p & 1;
            int k = chunk * 16 + 2 * tt + 8 * bb + jj;
            unsigned short h, l;
            split_f16(w[k * DIM + n], h, l);
            hiB[j] = h; loB[j] = l;
        }
    }
}

// ----------------------- multi-block CSR scan (2 phases) --------------------
__global__ void scan_part_kernel(int n) {
    __shared__ int red[8];
    int b = blockIdx.x, t = threadIdx.x;
    int i = b * 256 + t;
    int v = (i < n) ? g_cnt[i] : 0;
    int s = v;
#pragma unroll
    for (int o = 16; o; o >>= 1) s += __shfl_xor_sync(0xffffffffu, s, o);
    if ((t & 31) == 0) red[t >> 5] = s;
    __syncthreads();
    if (t == 0) {
        int tot = 0;
#pragma unroll
        for (int j = 0; j < 8; ++j) tot += red[j];
        g_part[b] = tot;
    }
}

__global__ void scan_bcast_kernel(int n, int nblk) {
    __shared__ int s[256];
    __shared__ int s_base[8];
    int b = blockIdx.x, t = threadIdx.x;
    int i = b * 256 + t;
    int v = (i < n) ? g_cnt[i] : 0;

    int acc = 0;
    for (int j = t; j < b; j += 256) acc += __ldg(&g_part[j]);
#pragma unroll
    for (int o = 16; o; o >>= 1) acc += __shfl_xor_sync(0xffffffffu, acc, o);
    if ((t & 31) == 0) s_base[t >> 5] = acc;

    s[t] = v;
    __syncthreads();
#pragma unroll
    for (int d = 1; d < 256; d <<= 1) {
        int vv = (t >= d) ? s[t - d] : 0;
        __syncthreads();
        s[t] += vv;
        __syncthreads();
    }
    int base = 0;
#pragma unroll
    for (int j = 0; j < 8; ++j) base += s_base[j];
    int excl = s[t] - v;
    if (i < n) {
        int r = base + excl;
        g_rowp[i] = r; g_cursor[i] = r;
        g_cnt[i] = 0;
        if (i == n - 1) g_rowp[n] = r + v;
    }
}

__global__ void fill_kernel(const void* __restrict__ eiv, int E) {
    __shared__ int s_ef;
    if (threadIdx.x == 0) s_ef = detect_ei((const unsigned int*)eiv);
    __syncthreads();
    int base = blockIdx.x * 1024 + threadIdx.x * 4;
    if (base >= E) return;
    int s[4], d[4];
    load4_idx(eiv, s_ef, base, 0, s);
    load4_idx(eiv, s_ef, base, E, d);
#pragma unroll
    for (int i = 0; i < 4; ++i) {
        int pos = atomicAdd(&g_cursor[d[i]], 1);
        g_srcs[pos] = s[i];
    }
}

// agg[v] = feat[v] + sum feat[src]; result written as fp16 hi/lo planes.
__global__ void gather_kernel(const float* __restrict__ feat, int n) {
    int g = blockIdx.x * blockDim.x + threadIdx.x;
    int v = g >> 5;
    if (v >= n) return;
    int lane = g & 31;
    float4 acc = ((const float4*)(feat + (size_t)v * DIM))[lane];
    int s0 = __ldg(&g_rowp[v]), s1 = __ldg(&g_rowp[v + 1]);
    if (s0 < s1) {
        int sCur = __ldg(&g_srcs[s0]);
        for (int e = s0; e < s1; ++e) {
            int sNext = (e + 1 < s1) ? __ldg(&g_srcs[e + 1]) : 0;
            float4 x = ((const float4*)(feat + (size_t)sCur * DIM))[lane];
            acc.x += x.x; acc.y += x.y; acc.z += x.z; acc.w += x.w;
            sCur = sNext;
        }
    }
    unsigned short h0, h1, h2, h3, l0, l1, l2, l3;
    split_f16(acc.x, h0, l0); split_f16(acc.y, h1, l1);
    split_f16(acc.z, h2, l2); split_f16(acc.w, h3, l3);
    ((uint2*)(g_ahi + (size_t)v * DIM))[lane] =
        make_uint2((unsigned)h0 | ((unsigned)h1 << 16), (unsigned)h2 | ((unsigned)h3 << 16));
    ((uint2*)(g_alo + (size_t)v * DIM))[lane] =
        make_uint2((unsigned)l0 | ((unsigned)l1 << 16), (unsigned)l2 | ((unsigned)l3 << 16));
}

// ----------------------------- shared MLP code ------------------------------
// pure copy: hi/lo planes (global) -> given smem A buffer (no ALU)
__device__ __forceinline__ void load_a_tile(int row0, int M, char* buf) {
    int t = threadIdx.x;
#pragma unroll
    for (int i = 0; i < 8; ++i) {
        int idx4 = i * 256 + t;
        int r = idx4 >> 5;
        int k = (idx4 & 31) << 2;
        uint2 hv = make_uint2(0u, 0u), lv = make_uint2(0u, 0u);
        if (row0 + r < M) {
            hv = __ldg((const uint2*)(g_ahi + (size_t)(row0 + r) * DIM + k));
            lv = __ldg((const uint2*)(g_alo + (size_t)(row0 + r) * DIM + k));
        }
        unsigned off = (unsigned)(r * AS_STRIDE + k) * 2;
        *(uint2*)(buf + off) = hv;
        *(uint2*)(buf + OFF_ALO + off) = lv;
    }
}

// GEMM over this warp's 2 m-tiles x 4 n-tiles: acc[0..3]=mt0, acc[4..7]=mt1.
__device__ __forceinline__ void gemm64(float (*acc)[4], unsigned aBase0,
                                       unsigned aBase1, const char* __restrict__ wb,
                                       unsigned bbase) {
#pragma unroll
    for (int ks = 0; ks < 8; ++ks) {
        unsigned ah0[4], al0[4], ah1[4], al1[4];
        ldm4(ah0, aBase0 + ks * 32);
        ldm4(al0, aBase0 + OFF_ALO + ks * 32);
        ldm4(ah1, aBase1 + ks * 32);
        ldm4(al1, aBase1 + OFF_ALO + ks * 32);
        uint2 bh[4];
#pragma unroll
        for (int j = 0; j < 4; ++j)
            bh[j] = __ldg((const uint2*)(wb + bbase + j * NT_STEP_B + ks * 32));
#pragma unroll
        for (int j = 0; j < 4; ++j) {
            mma_hf(acc[j],     ah0, bh[j]);
            mma_hf(acc[4 + j], ah1, bh[j]);
        }
#pragma unroll
        for (int j = 0; j < 4; ++j) {
            mma_hf(acc[j],     al0, bh[j]);
            mma_hf(acc[4 + j], al1, bh[j]);
        }
#pragma unroll
        for (int j = 0; j < 4; ++j)
            bh[j] = __ldg((const uint2*)(wb + W_ONE_B + bbase + j * NT_STEP_B + ks * 32));
#pragma unroll
        for (int j = 0; j < 4; ++j) {
            mma_hf(acc[j],     ah0, bh[j]);
            mma_hf(acc[4 + j], ah1, bh[j]);
        }
    }
}

// ----------------------------- fused MLP kernels ----------------------------
// Persistent: each block loops tiles with stride gridDim.x; A double-buffered
// on the BLOCK-LOCAL iteration parity ib (alternates every iteration).
__global__ __launch_bounds__(256, 2)
void mlp1_kernel(const float* __restrict__ b1g, const float* __restrict__ b2g,
                 float* __restrict__ H, int M, int tiles) {
    extern __shared__ char dsm[];
    __shared__ float s_b1[128], s_b2[128];

    const int t = threadIdx.x;
    const int lane = t & 31;
    const int warp = t >> 5;              // 0..7
    const int mw   = warp & 1;
    const int ng   = warp >> 1;
    const unsigned smb = smem_u32(dsm);

    if (t < 128) { s_b1[t] = b1g[t]; s_b2[t] = b2g[t]; }

    const unsigned aOffW = (unsigned)(mw * 32 + (lane & 15)) * (AS_STRIDE * 2)
                         + (unsigned)(lane >> 4) * 16;
    const unsigned bbase = (unsigned)(lane >> 2) * (WS_STRIDE * 2)
                         + (unsigned)(lane & 3) * 8
                         + (unsigned)(ng * 4) * NT_STEP_B;
    const char* wb0 = (const char*)g_wblob;
    const int tq = lane & 3;
    const int g  = lane >> 2;

    int it = blockIdx.x;
    if (it >= tiles) return;
    int ib = 0;                            // block-local buffer parity
    load_a_tile(it * TROWS, M, dsm);       // tile -> buffer 0
    __syncthreads();

    for (; it < tiles; it += gridDim.x, ib ^= 1) {
        const int row0 = it * TROWS;
        const unsigned bufO = (unsigned)ib * ABUF_B;
        const unsigned aBase0 = smb + bufO + aOffW;
        const unsigned aBase1 = aBase0 + 16 * (AS_STRIDE * 2);
        const int nxt = it + gridDim.x;

        // ---- GEMM1 ----
        float acc1[8][4];
#pragma unroll
        for (int q = 0; q < 8; ++q)
#pragma unroll
            for (int j = 0; j < 4; ++j) acc1[q][j] = 0.f;
        gemm64(acc1, aBase0, aBase1, wb0, bbase);
        __syncthreads();   // A reads done before rewrite/prefetch

        // ---- epilogue1 -> current buffer; prefetch next tile -> other ----
#pragma unroll
        for (int q = 0; q < 8; ++q) {
            int i  = q >> 2;
            int j  = q & 3;
            int col  = (ng * 4 + j) * 8 + 2 * tq;
            int rowA = (mw * 2 + i) * 16 + g;
            float v0 = fmaxf(acc1[q][0] + s_b1[col],     0.f);
            float v1 = fmaxf(acc1[q][1] + s_b1[col + 1], 0.f);
            float v2 = fmaxf(acc1[q][2] + s_b1[col],     0.f);
            float v3 = fmaxf(acc1[q][3] + s_b1[col + 1], 0.f);
            unsigned short h0, h1, h2, h3, l0, l1, l2, l3;
            split_f16(v0, h0, l0); split_f16(v1, h1, l1);
            split_f16(v2, h2, l2); split_f16(v3, h3, l3);
            unsigned offA = bufO + (unsigned)(rowA * AS_STRIDE + col) * 2;
            unsigned offB = bufO + (unsigned)((rowA + 8) * AS_STRIDE + col) * 2;
            sts32(smb + offA, (unsigned)h0 | ((unsigned)h1 << 16));
            sts32(smb + offB, (unsigned)h2 | ((unsigned)h3 << 16));
            sts32(smb + OFF_ALO + offA, (unsigned)l0 | ((unsigned)l1 << 16));
            sts32(smb + OFF_ALO + offB, (unsigned)l2 | ((unsigned)l3 << 16));
        }
        if (nxt < tiles)
            load_a_tile(nxt * TROWS, M, dsm + (ib ^ 1) * ABUF_B);
        __syncthreads();

        // ---- GEMM2 ----
        float acc2[8][4];
#pragma unroll
        for (int q = 0; q < 8; ++q)
#pragma unroll
            for (int j = 0; j < 4; ++j) acc2[q][j] = 0.f;
        gemm64(acc2, aBase0, aBase1, wb0 + W_PAIR_B, bbase);

        // ---- epilogue2 -> global ----
#pragma unroll
        for (int q = 0; q < 8; ++q) {
            int i  = q >> 2;
            int j  = q & 3;
            int col  = (ng * 4 + j) * 8 + 2 * tq;
            int rowA = row0 + (mw * 2 + i) * 16 + g;
            int rowB = rowA + 8;
            if (rowA < M)
                *(float2*)(H + (size_t)rowA * DIM + col) =
                    make_float2(acc2[q][0] + s_b2[col], acc2[q][1] + s_b2[col + 1]);
            if (rowB < M)
                *(float2*)(H + (size_t)rowB * DIM + col) =
                    make_float2(acc2[q][2] + s_b2[col], acc2[q][3] + s_b2[col + 1]);
        }
        __syncthreads();   // GEMM2 reads done before next iter rewrites buffers
    }
}

__global__ __launch_bounds__(256, 2)
void mlp2_kernel(const float* __restrict__ bag, float* __restrict__ out,
                 int M, int tiles) {
    extern __shared__ char dsm[];
    __shared__ float s_b[128], s_wv[128], s_part[TROWS];

    const int t = threadIdx.x;
    const int lane = t & 31;
    const int warp = t >> 5;
    const int mw   = warp & 1;
    const int ng   = warp >> 1;
    const unsigned smb = smem_u32(dsm);

    if (t < 128) { s_b[t] = bag[t]; s_wv[t] = g_wv[t]; }
    if (t < TROWS) s_part[t] = 0.f;

    const unsigned aOffW = (unsigned)(mw * 32 + (lane & 15)) * (AS_STRIDE * 2)
                         + (unsigned)(lane >> 4) * 16;
    const unsigned bbase = (unsigned)(lane >> 2) * (WS_STRIDE * 2)
                         + (unsigned)(lane & 3) * 8
                         + (unsigned)(ng * 4) * NT_STEP_B;
    const char* wb2 = (const char*)g_wblob + 2 * W_PAIR_B;
    const int tq = lane & 3;
    const int g  = lane >> 2;

    int it = blockIdx.x;
    if (it >= tiles) return;
    int ib = 0;
    load_a_tile(it * TROWS, M, dsm);
    __syncthreads();

    for (; it < tiles; it += gridDim.x, ib ^= 1) {
        const int row0 = it * TROWS;
        const unsigned bufO = (unsigned)ib * ABUF_B;
        const unsigned aBase0 = smb + bufO + aOffW;
        const unsigned aBase1 = aBase0 + 16 * (AS_STRIDE * 2);
        const int nxt = it + gridDim.x;

        float acc[8][4];
#pragma unroll
        for (int q = 0; q < 8; ++q)
#pragma unroll
            for (int j = 0; j < 4; ++j) acc[q][j] = 0.f;
        gemm64(acc, aBase0, aBase1, wb2, bbase);
        __syncthreads();   // A reads done before prefetch overwrite

        if (nxt < tiles)
            load_a_tile(nxt * TROWS, M, dsm + (ib ^ 1) * ABUF_B);

        // fused head: partial dot over this warp's 32 columns
        float p[2][2] = {{0.f, 0.f}, {0.f, 0.f}};
#pragma unroll
        for (int q = 0; q < 8; ++q) {
            int i  = q >> 2;
            int j  = q & 3;
            int col = (ng * 4 + j) * 8 + 2 * tq;
            float w0 = s_wv[col], w1 = s_wv[col + 1];
            float b0 = s_b[col],  b1 = s_b[col + 1];
            p[i][0] += fmaxf(acc[q][0] + b0, 0.f) * w0 + fmaxf(acc[q][1] + b1, 0.f) * w1;
            p[i][1] += fmaxf(acc[q][2] + b0, 0.f) * w0 + fmaxf(acc[q][3] + b1, 0.f) * w1;
        }
#pragma unroll
        for (int i = 0; i < 2; ++i)
#pragma unroll
            for (int hh = 0; hh < 2; ++hh) {
                float v = p[i][hh];
                v += __shfl_xor_sync(0xffffffffu, v, 1);
                v += __shfl_xor_sync(0xffffffffu, v, 2);
                p[i][hh] = v;
            }
        if (tq == 0) {
#pragma unroll
            for (int i = 0; i < 2; ++i) {
                int r = (mw * 2 + i) * 16 + g;
                atomicAdd(&s_part[r], p[i][0]);
                atomicAdd(&s_part[r + 8], p[i][1]);
            }
        }
        __syncthreads();
        if (t < TROWS) {
            if (row0 + t < M) out[row0 + t] = s_part[t] + g_cb;
            s_part[t] = 0.f;                     // reset for next iteration
        }
        __syncthreads();
    }
}

// ---------------------------------------------------------------------------
extern "C" void kernel_launch(void* const* d_in, const int* in_sizes, int n_in,
                              void* d_out, int out_size) {
    const float* x   = (const float*)d_in[0];
    const void*  ei  = d_in[1];
    const float* w1a = (const float*)d_in[2];
    const float* b1a = (const float*)d_in[3];
    const float* w1b = (const float*)d_in[4];
    const float* b1b = (const float*)d_in[5];
    const float* w2a = (const float*)d_in[6];
    const float* b2a = (const float*)d_in[7];
    const float* w2b = (const float*)d_in[8];
    const float* b2b = (const float*)d_in[9];
    const float* wo  = (const float*)d_in[10];
    const float* bo  = (const float*)d_in[11];
    float* out = (float*)d_out;

    const int M = in_sizes[0] / DIM;   // 100000
    const int E = in_sizes[1] / 2;     // 600000

    float* h1;
    cudaGetSymbolAddress((void**)&h1, g_h1);

    cudaFuncSetAttribute(mlp1_kernel, cudaFuncAttributeMaxDynamicSharedMemorySize, SMEM_MLP);
    cudaFuncSetAttribute(mlp2_kernel, cudaFuncAttributeMaxDynamicSharedMemorySize, SMEM_MLP);

    const int tiles       = (M + TROWS - 1) / TROWS;
    const int pgrid       = (tiles < PGRID) ? tiles : PGRID;
    const int edgeBlocks4 = (E + 1023) / 1024;
    const int scanBlocks  = (M + 255) / 256;
    const int gathBlocks  = (int)(((long long)M * 32 + 255) / 256);

    // 0: histogram (vectorized) + weight prep + head fold
    hist_setup_kernel<<<edgeBlocks4 + 217, 256>>>(ei, E, edgeBlocks4,
                                                  w1a, w1b, w2a, w2b, b2b, wo, bo);
    // 1, 2: multi-block scan
    scan_part_kernel <<<scanBlocks, 256>>>(M);
    scan_bcast_kernel<<<scanBlocks, 256>>>(M, scanBlocks);
    // 3: fill (vectorized)  <- profiled
    fill_kernel<<<edgeBlocks4, 256>>>(ei, E);
    // 4, 5: layer 1 (persistent, double-buffered)
    gather_kernel<<<gathBlocks, 256>>>(x, M);
    mlp1_kernel<<<pgrid, 256, SMEM_MLP>>>(b1a, b1b, h1, M, tiles);
    // 6, 7: layer 2 + folded head (persistent, double-buffered)
    gather_kernel<<<gathBlocks, 256>>>(h1, M);
    mlp2_kernel<<<pgrid, 256, SMEM_MLP>>>(b2a, out, M, tiles);
}

// round 17
// speedup vs baseline: 1.1407x; 1.1407x over previous
#include <cuda_runtime.h>
#include <cuda_fp16.h>

// ---------------------------------------------------------------------------
// GIN regressor (sm_103): HMMA fp16 3-pass split GEMMs + CSR gather.
// R17 = R14 (best, 190.9us) with MLP blocks reshaped 256thr/64rows ->
// 128thr/32rows: identical per-warp work & total L1 bytes, but 4 independent
// blocks/SM (was 2) -> serial load/epilogue phases hidden by 3 other blocks,
// 4-warp barriers, finer wave tail. Persistence (R16, +23us) reverted.
// Launches: hist+setup(0) scan_part(1) scan_bcast(2) fill(3)<-profiled
//           gather(4) mlp1(5) gather(6) mlp2(7)
// ---------------------------------------------------------------------------

#define NODES 100000
#define EMAX  600000
#define DIM   128
#define SCAN_BLKS ((NODES + 255) / 256)          // 391

__device__ __align__(16) unsigned short g_ahi[NODES * DIM];  // split agg, hi plane
__device__ __align__(16) unsigned short g_alo[NODES * DIM];  // split agg, lo plane
__device__ __align__(16) float g_h1 [NODES * DIM];
__device__ __align__(16) unsigned short g_wblob[3 * 2 * 128 * 144];
__device__ __align__(16) float g_wv[DIM];
__device__ float g_cb;
__device__ int   g_cnt[NODES];          // zero-init; scan_bcast resets
__device__ int   g_part[SCAN_BLKS];
__device__ int   g_rowp[NODES + 1];
__device__ int   g_cursor[NODES];
__device__ int   g_srcs[EMAX];

// ------------------------------ helpers ------------------------------------
__device__ __forceinline__ unsigned smem_u32(const void* p) {
    unsigned a;
    asm("{ .reg .u64 t; cvta.to.shared.u64 t, %1; cvt.u32.u64 %0, t; }"
        : "=r"(a) : "l"(p));
    return a;
}
// volatile+memory: A smem rewritten by epilogue1, re-read at same addresses.
__device__ __forceinline__ void ldm4(unsigned* r, unsigned addr) {
    asm volatile("ldmatrix.sync.aligned.m8n8.x4.shared.b16 {%0,%1,%2,%3}, [%4];"
                 : "=r"(r[0]), "=r"(r[1]), "=r"(r[2]), "=r"(r[3]) : "r"(addr)
                 : "memory");
}
__device__ __forceinline__ void sts32(unsigned addr, unsigned v) {
    asm volatile("st.shared.u32 [%0], %1;" :: "r"(addr), "r"(v) : "memory");
}
__device__ __forceinline__ void mma_hf(float* c, const unsigned* a, uint2 b) {
    asm ("mma.sync.aligned.m16n8k16.row.col.f32.f16.f16.f32 "
         "{%0,%1,%2,%3}, {%4,%5,%6,%7}, {%8,%9}, {%0,%1,%2,%3};"
         : "+f"(c[0]), "+f"(c[1]), "+f"(c[2]), "+f"(c[3])
         : "r"(a[0]), "r"(a[1]), "r"(a[2]), "r"(a[3]), "r"(b.x), "r"(b.y));
}
__device__ __forceinline__ void split_f16(float a, unsigned short& hi, unsigned short& lo) {
    __half h = __float2half_rn(a);
    hi = __half_as_ushort(h);
    lo = __half_as_ushort(__float2half_rn(a - __half2float(h)));
}

#define AS_STRIDE 136
#define WS_STRIDE 144
#define W_ONE     (128 * WS_STRIDE)
#define W_ONE_B   (W_ONE * 2)           // 36864
#define W_PAIR_B  (2 * W_ONE_B)         // 73728

#define TROWS 32                                // MLP tile rows
#define OFF_ALO  (TROWS * AS_STRIDE * 2)        // 8704 (within smem)
#define SMEM_MLP (2 * TROWS * AS_STRIDE * 2)    // 17408 -> 4 blocks/SM

#define NT_STEP_B (8 * WS_STRIDE * 2)           // 2304

// ------------------------- hist + setup (launch 0) ---------------------------
__device__ __forceinline__ int detect_ei(const unsigned int* ei) {
    unsigned orv = 0;
#pragma unroll
    for (int i = 0; i < 64; ++i) orv |= ei[2 * i + 1];
    return (orv == 0u) ? 1 : 0;
}

// 4 edges per thread; E % 4 == 0 so groups are all-or-nothing.
__device__ __forceinline__ void load4_idx(const void* eiv, int ef, int base,
                                          int off, int* d) {
    if (ef) {
        const long long* p = (const long long*)eiv + off + base;
        longlong2 a = *(const longlong2*)p;
        longlong2 b = *(const longlong2*)(p + 2);
        d[0] = (int)a.x; d[1] = (int)a.y; d[2] = (int)b.x; d[3] = (int)b.y;
    } else {
        const int* p = (const int*)eiv + off + base;
        int4 a = *(const int4*)p;
        d[0] = a.x; d[1] = a.y; d[2] = a.z; d[3] = a.w;
    }
}

__global__ void hist_setup_kernel(const void* __restrict__ eiv, int E, int edgeBlocks,
                                  const float* __restrict__ w1a,
                                  const float* __restrict__ w1b,
                                  const float* __restrict__ w2a,
                                  const float* __restrict__ w2b,
                                  const float* __restrict__ b2b,
                                  const float* __restrict__ wo,
                                  const float* __restrict__ bo) {
    int b = blockIdx.x, t = threadIdx.x;
    if (b < edgeBlocks) {                       // histogram: 1024 edges/block
        __shared__ int s_ef;
        if (t == 0) s_ef = detect_ei((const unsigned int*)eiv);
        __syncthreads();
        int base = b * 1024 + t * 4;
        if (base >= E) return;
        int d[4];
        load4_idx(eiv, s_ef, base, E, d);
        atomicAdd(&g_cnt[d[0]], 1);
        atomicAdd(&g_cnt[d[1]], 1);
        atomicAdd(&g_cnt[d[2]], 1);
        atomicAdd(&g_cnt[d[3]], 1);
        return;
    }
    int sb = b - edgeBlocks;                    // setup part
    if (sb == 0) {
        if (t < 128) {
            float s = 0.f;
#pragma unroll 8
            for (int n = 0; n < DIM; ++n) s += w2b[t * DIM + n] * wo[n];
            g_wv[t] = s;
            if (t == 0) {
                float c = bo[0];
                for (int n = 0; n < DIM; ++n) c += b2b[n] * wo[n];
                g_cb = c;
            }
        }
    } else {
        int i = (sb - 1) * 256 + t;
        int slot = i / W_ONE;
        int j    = i - slot * W_ONE;
        const float* w = (slot == 0) ? w1a : (slot == 1) ? w1b : w2a;
        unsigned short* hiB = g_wblob + (size_t)slot * 2 * W_ONE;
        unsigned short* loB = hiB + W_ONE;
        int n  = j / WS_STRIDE;
        int kp = j - n * WS_STRIDE;
        if (kp >= 128) { hiB[j] = 0; loB[j] = 0; }
        else {
            int chunk = kp >> 4, p = kp & 15;
            int tt = p >> 2, bb = (p >> 1) & 1, jj = p & 1;
            int k = chunk * 16 + 2 * tt + 8 * bb + jj;
            unsigned short h, l;
            split_f16(w[k * DIM + n], h, l);
            hiB[j] = h; loB[j] = l;
        }
    }
}

// ----------------------- multi-block CSR scan (2 phases) --------------------
__global__ void scan_part_kernel(int n) {
    __shared__ int red[8];
    int b = blockIdx.x, t = threadIdx.x;
    int i = b * 256 + t;
    int v = (i < n) ? g_cnt[i] : 0;
    int s = v;
#pragma unroll
    for (int o = 16; o; o >>= 1) s += __shfl_xor_sync(0xffffffffu, s, o);
    if ((t & 31) == 0) red[t >> 5] = s;
    __syncthreads();
    if (t == 0) {
        int tot = 0;
#pragma unroll
        for (int j = 0; j < 8; ++j) tot += red[j];
        g_part[b] = tot;
    }
}

__global__ void scan_bcast_kernel(int n, int nblk) {
    __shared__ int s[256];
    __shared__ int s_base[8];
    int b = blockIdx.x, t = threadIdx.x;
    int i = b * 256 + t;
    int v = (i < n) ? g_cnt[i] : 0;

    int acc = 0;
    for (int j = t; j < b; j += 256) acc += __ldg(&g_part[j]);
#pragma unroll
    for (int o = 16; o; o >>= 1) acc += __shfl_xor_sync(0xffffffffu, acc, o);
    if ((t & 31) == 0) s_base[t >> 5] = acc;

    s[t] = v;
    __syncthreads();
#pragma unroll
    for (int d = 1; d < 256; d <<= 1) {
        int vv = (t >= d) ? s[t - d] : 0;
        __syncthreads();
        s[t] += vv;
        __syncthreads();
    }
    int base = 0;
#pragma unroll
    for (int j = 0; j < 8; ++j) base += s_base[j];
    int excl = s[t] - v;
    if (i < n) {
        int r = base + excl;
        g_rowp[i] = r; g_cursor[i] = r;
        g_cnt[i] = 0;
        if (i == n - 1) g_rowp[n] = r + v;
    }
}

__global__ void fill_kernel(const void* __restrict__ eiv, int E) {
    __shared__ int s_ef;
    if (threadIdx.x == 0) s_ef = detect_ei((const unsigned int*)eiv);
    __syncthreads();
    int base = blockIdx.x * 1024 + threadIdx.x * 4;
    if (base >= E) return;
    int s[4], d[4];
    load4_idx(eiv, s_ef, base, 0, s);
    load4_idx(eiv, s_ef, base, E, d);
#pragma unroll
    for (int i = 0; i < 4; ++i) {
        int pos = atomicAdd(&g_cursor[d[i]], 1);
        g_srcs[pos] = s[i];
    }
}

// agg[v] = feat[v] + sum feat[src]; result written as fp16 hi/lo planes.
__global__ void gather_kernel(const float* __restrict__ feat, int n) {
    int g = blockIdx.x * blockDim.x + threadIdx.x;
    int v = g >> 5;
    if (v >= n) return;
    int lane = g & 31;
    float4 acc = ((const float4*)(feat + (size_t)v * DIM))[lane];
    int s0 = __ldg(&g_rowp[v]), s1 = __ldg(&g_rowp[v + 1]);
    if (s0 < s1) {
        int sCur = __ldg(&g_srcs[s0]);
        for (int e = s0; e < s1; ++e) {
            int sNext = (e + 1 < s1) ? __ldg(&g_srcs[e + 1]) : 0;
            float4 x = ((const float4*)(feat + (size_t)sCur * DIM))[lane];
            acc.x += x.x; acc.y += x.y; acc.z += x.z; acc.w += x.w;
            sCur = sNext;
        }
    }
    unsigned short h0, h1, h2, h3, l0, l1, l2, l3;
    split_f16(acc.x, h0, l0); split_f16(acc.y, h1, l1);
    split_f16(acc.z, h2, l2); split_f16(acc.w, h3, l3);
    ((uint2*)(g_ahi + (size_t)v * DIM))[lane] =
        make_uint2((unsigned)h0 | ((unsigned)h1 << 16), (unsigned)h2 | ((unsigned)h3 << 16));
    ((uint2*)(g_alo + (size_t)v * DIM))[lane] =
        make_uint2((unsigned)l0 | ((unsigned)l1 << 16), (unsigned)l2 | ((unsigned)l3 << 16));
}

// ----------------------------- shared MLP code ------------------------------
// pure copy: hi/lo planes (global) -> smem A buffer (no ALU); 128 threads.
__device__ __forceinline__ void load_a_tile(int row0, int M, char* dsm) {
    int t = threadIdx.x;
#pragma unroll
    for (int i = 0; i < 8; ++i) {
        int idx4 = i * 128 + t;                 // 0..1023
        int r = idx4 >> 5;                      // 0..31
        int k = (idx4 & 31) << 2;
        uint2 hv = make_uint2(0u, 0u), lv = make_uint2(0u, 0u);
        if (row0 + r < M) {
            hv = __ldg((const uint2*)(g_ahi + (size_t)(row0 + r) * DIM + k));
            lv = __ldg((const uint2*)(g_alo + (size_t)(row0 + r) * DIM + k));
        }
        unsigned off = (unsigned)(r * AS_STRIDE + k) * 2;
        *(uint2*)(dsm + off) = hv;
        *(uint2*)(dsm + OFF_ALO + off) = lv;
    }
}

// GEMM over this warp's 2 m-tiles x 4 n-tiles: acc[0..3]=mt0, acc[4..7]=mt1.
// B fragments batched (4 live) so dependent MMAs on one acc are 8 slots apart.
__device__ __forceinline__ void gemm64(float (*acc)[4], unsigned aBase0,
                                       unsigned aBase1, const char* __restrict__ wb,
                                       unsigned bbase) {
#pragma unroll
    for (int ks = 0; ks < 8; ++ks) {
        unsigned ah0[4], al0[4], ah1[4], al1[4];
        ldm4(ah0, aBase0 + ks * 32);
        ldm4(al0, aBase0 + OFF_ALO + ks * 32);
        ldm4(ah1, aBase1 + ks * 32);
        ldm4(al1, aBase1 + OFF_ALO + ks * 32);
        uint2 bh[4];
#pragma unroll
        for (int j = 0; j < 4; ++j)
            bh[j] = __ldg((const uint2*)(wb + bbase + j * NT_STEP_B + ks * 32));
#pragma unroll
        for (int j = 0; j < 4; ++j) {
            mma_hf(acc[j],     ah0, bh[j]);
            mma_hf(acc[4 + j], ah1, bh[j]);
        }
#pragma unroll
        for (int j = 0; j < 4; ++j) {
            mma_hf(acc[j],     al0, bh[j]);
            mma_hf(acc[4 + j], al1, bh[j]);
        }
#pragma unroll
        for (int j = 0; j < 4; ++j)
            bh[j] = __ldg((const uint2*)(wb + W_ONE_B + bbase + j * NT_STEP_B + ks * 32));
#pragma unroll
        for (int j = 0; j < 4; ++j) {
            mma_hf(acc[j],     ah0, bh[j]);
            mma_hf(acc[4 + j], ah1, bh[j]);
        }
    }
}

// ----------------------------- fused MLP kernels ----------------------------
// 128 threads = 4 warps; warp w handles n-tiles w*4..w*4+3 over all 32 rows.
__global__ __launch_bounds__(128, 4)
void mlp1_kernel(const float* __restrict__ b1g, const float* __restrict__ b2g,
                 float* __restrict__ H, int M) {
    extern __shared__ char dsm[];
    __shared__ float s_b1[128], s_b2[128];

    const int t = threadIdx.x;
    const int lane = t & 31;
    const int ng   = t >> 5;              // 0..3 n-quarter
    const int row0 = blockIdx.x * TROWS;
    const unsigned smb = smem_u32(dsm);

    s_b1[t] = b1g[t]; s_b2[t] = b2g[t];
    load_a_tile(row0, M, dsm);
    __syncthreads();

    const unsigned aBase0 = smb + (unsigned)(lane & 15) * (AS_STRIDE * 2)
                          + (unsigned)(lane >> 4) * 16;
    const unsigned aBase1 = aBase0 + 16 * (AS_STRIDE * 2);
    const unsigned bbase = (unsigned)(lane >> 2) * (WS_STRIDE * 2)
                         + (unsigned)(lane & 3) * 8
                         + (unsigned)(ng * 4) * NT_STEP_B;
    const char* wb0 = (const char*)g_wblob;

    // ---- GEMM1: T1 = agg @ w1a' ----
    float acc1[8][4];
#pragma unroll
    for (int q = 0; q < 8; ++q)
#pragma unroll
        for (int j = 0; j < 4; ++j) acc1[q][j] = 0.f;
    gemm64(acc1, aBase0, aBase1, wb0, bbase);
    __syncthreads();   // all GEMM1 A-reads done before rewrites

    // ---- epilogue1: T1 = relu(C+b1a) -> A buffers (fp16 split) ----
    const int tq = lane & 3;
    const int g  = lane >> 2;
#pragma unroll
    for (int q = 0; q < 8; ++q) {
        int i  = q >> 2;                          // m-sub (0/1)
        int j  = q & 3;                           // n-sub
        int col  = (ng * 4 + j) * 8 + 2 * tq;
        int rowA = i * 16 + g;                    // 0..31
        float v0 = fmaxf(acc1[q][0] + s_b1[col],     0.f);
        float v1 = fmaxf(acc1[q][1] + s_b1[col + 1], 0.f);
        float v2 = fmaxf(acc1[q][2] + s_b1[col],     0.f);
        float v3 = fmaxf(acc1[q][3] + s_b1[col + 1], 0.f);
        unsigned short h0, h1, h2, h3, l0, l1, l2, l3;
        split_f16(v0, h0, l0); split_f16(v1, h1, l1);
        split_f16(v2, h2, l2); split_f16(v3, h3, l3);
        unsigned offA = (unsigned)(rowA * AS_STRIDE + col) * 2;
        unsigned offB = (unsigned)((rowA + 8) * AS_STRIDE + col) * 2;
        sts32(smb + offA, (unsigned)h0 | ((unsigned)h1 << 16));
        sts32(smb + offB, (unsigned)h2 | ((unsigned)h3 << 16));
        sts32(smb + OFF_ALO + offA, (unsigned)l0 | ((unsigned)l1 << 16));
        sts32(smb + OFF_ALO + offB, (unsigned)l2 | ((unsigned)l3 << 16));
    }
    __syncthreads();

    // ---- GEMM2: h1 = T1 @ w1b' ----
    float acc2[8][4];
#pragma unroll
    for (int q = 0; q < 8; ++q)
#pragma unroll
        for (int j = 0; j < 4; ++j) acc2[q][j] = 0.f;
    gemm64(acc2, aBase0, aBase1, wb0 + W_PAIR_B, bbase);

    // ---- epilogue2: h1 = C + b1b -> global (fp32 for gather2) ----
#pragma unroll
    for (int q = 0; q < 8; ++q) {
        int i  = q >> 2;
        int j  = q & 3;
        int col  = (ng * 4 + j) * 8 + 2 * tq;
        int rowA = row0 + i * 16 + g;
        int rowB = rowA + 8;
        if (rowA < M)
            *(float2*)(H + (size_t)rowA * DIM + col) =
                make_float2(acc2[q][0] + s_b2[col], acc2[q][1] + s_b2[col + 1]);
        if (rowB < M)
            *(float2*)(H + (size_t)rowB * DIM + col) =
                make_float2(acc2[q][2] + s_b2[col], acc2[q][3] + s_b2[col + 1]);
    }
}

__global__ __launch_bounds__(128, 4)
void mlp2_kernel(const float* __restrict__ bag, float* __restrict__ out, int M) {
    extern __shared__ char dsm[];
    __shared__ float s_b[128], s_wv[128], s_part[TROWS];

    const int t = threadIdx.x;
    const int lane = t & 31;
    const int ng   = t >> 5;
    const int row0 = blockIdx.x * TROWS;
    const unsigned smb = smem_u32(dsm);

    s_b[t] = bag[t]; s_wv[t] = g_wv[t];
    if (t < TROWS) s_part[t] = 0.f;
    load_a_tile(row0, M, dsm);
    __syncthreads();

    const unsigned aBase0 = smb + (unsigned)(lane & 15) * (AS_STRIDE * 2)
                          + (unsigned)(lane >> 4) * 16;
    const unsigned aBase1 = aBase0 + 16 * (AS_STRIDE * 2);
    const unsigned bbase = (unsigned)(lane >> 2) * (WS_STRIDE * 2)
                         + (unsigned)(lane & 3) * 8
                         + (unsigned)(ng * 4) * NT_STEP_B;
    const char* wb2 = (const char*)g_wblob + 2 * W_PAIR_B;

    float acc[8][4];
#pragma unroll
    for (int q = 0; q < 8; ++q)
#pragma unroll
        for (int j = 0; j < 4; ++j) acc[q][j] = 0.f;
    gemm64(acc, aBase0, aBase1, wb2, bbase);

    // fused head: partial dot over this warp's 32 columns, per row group
    const int tq = lane & 3;
    const int g  = lane >> 2;
    float p[2][2] = {{0.f, 0.f}, {0.f, 0.f}};     // [m-sub][row half]
#pragma unroll
    for (int q = 0; q < 8; ++q) {
        int i  = q >> 2;
        int j  = q & 3;
        int col = (ng * 4 + j) * 8 + 2 * tq;
        float w0 = s_wv[col], w1 = s_wv[col + 1];
        float b0 = s_b[col],  b1 = s_b[col + 1];
        p[i][0] += fmaxf(acc[q][0] + b0, 0.f) * w0 + fmaxf(acc[q][1] + b1, 0.f) * w1;
        p[i][1] += fmaxf(acc[q][2] + b0, 0.f) * w0 + fmaxf(acc[q][3] + b1, 0.f) * w1;
    }
#pragma unroll
    for (int i = 0; i < 2; ++i)
#pragma unroll
        for (int hh = 0; hh < 2; ++hh) {
            float v = p[i][hh];
            v += __shfl_xor_sync(0xffffffffu, v, 1);
            v += __shfl_xor_sync(0xffffffffu, v, 2);
            p[i][hh] = v;
        }
    if (tq == 0) {
#pragma unroll
        for (int i = 0; i < 2; ++i) {
            int r = i * 16 + g;
            atomicAdd(&s_part[r], p[i][0]);
            atomicAdd(&s_part[r + 8], p[i][1]);
        }
    }
    __syncthreads();
    if (t < TROWS && row0 + t < M) out[row0 + t] = s_part[t] + g_cb;
}

// ---------------------------------------------------------------------------
extern "C" void kernel_launch(void* const* d_in, const int* in_sizes, int n_in,
                              void* d_out, int out_size) {
    const float* x   = (const float*)d_in[0];
    const void*  ei  = d_in[1];
    const float* w1a = (const float*)d_in[2];
    const float* b1a = (const float*)d_in[3];
    const float* w1b = (const float*)d_in[4];
    const float* b1b = (const float*)d_in[5];
    const float* w2a = (const float*)d_in[6];
    const float* b2a = (const float*)d_in[7];
    const float* w2b = (const float*)d_in[8];
    const float* b2b = (const float*)d_in[9];
    const float* wo  = (const float*)d_in[10];
    const float* bo  = (const float*)d_in[11];
    float* out = (float*)d_out;

    const int M = in_sizes[0] / DIM;   // 100000
    const int E = in_sizes[1] / 2;     // 600000

    float* h1;
    cudaGetSymbolAddress((void**)&h1, g_h1);

    cudaFuncSetAttribute(mlp1_kernel, cudaFuncAttributeMaxDynamicSharedMemorySize, SMEM_MLP);
    cudaFuncSetAttribute(mlp2_kernel, cudaFuncAttributeMaxDynamicSharedMemorySize, SMEM_MLP);

    const int tiles       = (M + TROWS - 1) / TROWS;   // 3125
    const int edgeBlocks4 = (E + 1023) / 1024;
    const int scanBlocks  = (M + 255) / 256;
    const int gathBlocks  = (int)(((long long)M * 32 + 255) / 256);

    // 0: histogram (vectorized) + weight prep + head fold
    hist_setup_kernel<<<edgeBlocks4 + 217, 256>>>(ei, E, edgeBlocks4,
                                                  w1a, w1b, w2a, w2b, b2b, wo, bo);
    // 1, 2: multi-block scan
    scan_part_kernel <<<scanBlocks, 256>>>(M);
    scan_bcast_kernel<<<scanBlocks, 256>>>(M, scanBlocks);
    // 3: fill (vectorized)  <- profiled
    fill_kernel<<<edgeBlocks4, 256>>>(ei, E);
    // 4, 5: layer 1 (gather writes split planes; mlp1 copies them)
    gather_kernel<<<gathBlocks, 256>>>(x, M);
    mlp1_kernel<<<tiles, 128, SMEM_MLP>>>(b1a, b1b, h1, M);
    // 6, 7: layer 2 + folded head
    gather_kernel<<<gathBlocks, 256>>>(h1, M);
    mlp2_kernel<<<tiles, 128, SMEM_MLP>>>(b2a, out, M);
}